// round 15
// baseline (speedup 1.0000x reference)
#include <cuda_runtime.h>
#include <cuda_bf16.h>

// WTA2D: per (B,C) row of H*W=3136 fp32, t = 313th-largest, out = (t > x) ? x : 0.
//
// Single-shot, one CTA per row (grid 16384). R11 selection skeleton with:
//  - load chunks INTERLEAVED with classify (front-batched LDG 13 -> ~4, cuts
//    the B300 cross-CTA L1tex-queue spread),
//  - single-warp pick over the 1024-bucket window histogram (one less barrier).
// Fast path: count >=2.0, histogram [1.0,2.0) via (u>>13)&0x3FF (monotone),
// pick crossing bucket, gather <=64, parallel rank-count.
// Fallback (exact, any input): iterated raw-byte histogram rounds + bisection.

#define NROW 3136
#define KSEL 313u
#define WLO 0x3F800000u    // 1.0f
#define WHI 0x40000000u    // 2.0f

__device__ __forceinline__ unsigned u2k(unsigned u) {
    return (u & 0x80000000u) ? ~u : (u | 0x80000000u);
}
__device__ __forceinline__ float k2f(unsigned k) {
    unsigned v = (k & 0x80000000u) ? (k ^ 0x80000000u) : ~k;
    return __uint_as_float(v);
}

__global__ void __launch_bounds__(256, 6)
wta2d_kernel(const float* __restrict__ x, float* __restrict__ out) {
    const int tid  = threadIdx.x;
    const int lane = tid & 31;
    const int warp = tid >> 5;
    const bool has4 = (tid < 16);
    const size_t base = (size_t)blockIdx.x * NROW;

    __shared__ unsigned hist[1024];
    __shared__ unsigned aboveW[8];
    __shared__ unsigned gbuf[64];
    __shared__ unsigned sb_b, sb_rank, sb_m;
    __shared__ float sb_t;
    __shared__ int gcount;

    reinterpret_cast<uint4*>(hist)[tid] = make_uint4(0u, 0u, 0u, 0u);
    if (tid < 64) gbuf[tid] = 0u;
    if (tid == 0) { gcount = 0; sb_m = 0u; }

    const uint4* xin = reinterpret_cast<const uint4*>(x + base);
    unsigned u[16];

    // ---- chunk 0 load before the barrier (overlaps latency with bar drain) ----
    {
        uint4 f = xin[tid];
        u[0] = f.x; u[1] = f.y; u[2] = f.z; u[3] = f.w;
    }
    __syncthreads();                       // hist zeros visible

    // ---- interleaved: classify chunk s, load chunk s+1 ----
    unsigned ab = 0;
#pragma unroll
    for (int s = 0; s < 4; ++s) {
        // issue next chunk's load first (independent of classify below)
        if (s < 3) {
            int p = tid + (s + 1) * 256;
            if (s < 2 || has4) {
                uint4 f = xin[p];
                u[4*s+4] = f.x; u[4*s+5] = f.y; u[4*s+6] = f.z; u[4*s+7] = f.w;
            } else {
                u[4*s+4] = u[4*s+5] = u[4*s+6] = u[4*s+7] = 0u;
            }
        }
        bool cvalid = (s < 3) || has4;
#pragma unroll
        for (int j = 4*s; j < 4*s+4; ++j) {
            unsigned v = u[j];
            if (cvalid) {
                if (v - WHI < 0x40000000u) ++ab;              // [2.0, +inf) positives
                else if (v - WLO < (WHI - WLO)) atomicAdd(&hist[(v >> 13) & 0x3FFu], 1u);
            }
        }
    }
#pragma unroll
    for (int off = 16; off >= 1; off >>= 1)
        ab += __shfl_xor_sync(0xFFFFFFFFu, ab, off);
    if (lane == 0) aboveW[warp] = ab;
    __syncthreads();                       // hist + aboveW ready

    // ---- single-warp pick over 1024 buckets ----
    if (warp == 0) {
        unsigned above = 0;
#pragma unroll
        for (int w = 0; w < 8; ++w) above += aboveW[w];
        if (above >= KSEL) {
            if (lane == 0) sb_m = 0xFFFFFFFFu;   // force fallback
        } else {
            const unsigned rk = KSEL - above;
            const uint4* h4 = reinterpret_cast<const uint4*>(hist) + lane * 8;
            unsigned cc[32];
            unsigned tot = 0;
#pragma unroll
            for (int q = 0; q < 8; ++q) {
                uint4 v = h4[q];
                cc[4*q+0] = v.x; cc[4*q+1] = v.y; cc[4*q+2] = v.z; cc[4*q+3] = v.w;
                tot += v.x + v.y + v.z + v.w;
            }
            unsigned s = tot;              // suffix-inclusive over lanes (higher lane = higher value)
#pragma unroll
            for (int off = 1; off <= 16; off <<= 1) {
                unsigned v = __shfl_down_sync(0xFFFFFFFFu, s, off);
                if (lane + off < 32) s += v;
            }
            unsigned run = s - tot;        // counts at higher values
#pragma unroll
            for (int j = 31; j >= 0; --j) {
                unsigned nr = run + cc[j];
                if (nr >= rk && run < rk) {
                    sb_b    = (unsigned)(lane * 32 + j);
                    sb_rank = rk - run;
                    sb_m    = cc[j];
                }
                run = nr;
            }
            // if no crossing bucket inside window, sb_m stays 0 -> fallback
        }
    }
    __syncthreads();
    const unsigned m    = sb_m;
    const unsigned bsel = sb_b;
    const unsigned rin  = sb_rank;

    bool fb = (m == 0u) || (m > 64u);

    if (!fb) {
        // ---- gather bucket elems, parallel rank-count ----
#pragma unroll
        for (int j = 0; j < 16; ++j) {
            bool valid = (j < 12) || has4;
            unsigned v = u[j];
            if (valid && (v - WLO < (WHI - WLO)) && ((v >> 13) & 0x3FFu) == bsel)
                gbuf[atomicAdd(&gcount, 1)] = v;   // positives: raw order == value order
        }
        __syncthreads();
        if (tid < 64) {
            int n = gcount;
            if (tid < n) {
                unsigned k = gbuf[tid];
                unsigned g = 0, e = 0;
#pragma unroll
                for (int q = 0; q < 16; ++q) {
                    uint4 v = reinterpret_cast<const uint4*>(gbuf)[q];
                    g += (v.x > k) + (v.y > k) + (v.z > k) + (v.w > k);
                    e += (v.x == k) + (v.y == k) + (v.z == k) + (v.w == k);
                }
                if (g < rin && rin <= g + e) sb_t = __uint_as_float(k);
            }
        }
    }

    if (fb) {
        // ---- generic fallback: iterated raw-byte rounds (exact) ----
        hist[tid] = 0u;
        if (tid == 0) gcount = 0;
        __syncthreads();
#pragma unroll
        for (int j = 0; j < 16; ++j) {
            bool valid = (j < 12) || has4;
            if (valid) atomicAdd(&hist[u[j] >> 24], 1u);
        }
        __syncthreads();
        if (warp == 0) {
            int o0 = lane * 8;
            unsigned cc[8];
#pragma unroll
            for (int j = 0; j < 8; ++j) {
                int o = o0 + j;
                int u8 = (o < 128) ? (127 - o) : o;
                cc[j] = hist[u8];
            }
            unsigned tot = cc[0]+cc[1]+cc[2]+cc[3]+cc[4]+cc[5]+cc[6]+cc[7];
            unsigned p = tot;
#pragma unroll
            for (int off = 1; off <= 16; off <<= 1) {
                unsigned v = __shfl_up_sync(0xFFFFFFFFu, p, off);
                if (lane >= off) p += v;
            }
            unsigned run = p - tot;
#pragma unroll
            for (int j = 0; j < 8; ++j) {
                unsigned nr = run + cc[j];
                if (nr >= KSEL && run < KSEL) {
                    int o = o0 + j;
                    unsigned u8 = (o < 128) ? (unsigned)(127 - o) : (unsigned)o;
                    sb_b    = u8 | ((o >= 128) ? 256u : 0u);
                    sb_rank = KSEL - run;
                    sb_m    = cc[j];
                }
                run = nr;
            }
        }
        __syncthreads();
        const unsigned X = (sb_b & 256u) ? 0xFFu : 0u;
        unsigned U  = sb_b & 0xFFu;
        unsigned K  = X ? (255u - U) : (U + 128u);
        unsigned rk = sb_rank;
        unsigned mm = sb_m;
        int bits = 24;
        while (mm > 64u && bits > 0) {
            hist[tid] = 0u;
            __syncthreads();
#pragma unroll
            for (int j = 0; j < 16; ++j) {
                bool valid = (j < 12) || has4;
                if (valid && (u[j] >> bits) == U)
                    atomicAdd(&hist[((u[j] >> (bits - 8)) & 0xFFu) ^ X], 1u);
            }
            __syncthreads();
            if (warp == 0) {
                unsigned rcur = rk;
                const uint4* h4 = reinterpret_cast<const uint4*>(hist) + lane * 2;
                uint4 v0 = h4[0], v1 = h4[1];
                unsigned cc[8] = { v0.x, v0.y, v0.z, v0.w, v1.x, v1.y, v1.z, v1.w };
                unsigned tot = cc[0]+cc[1]+cc[2]+cc[3]+cc[4]+cc[5]+cc[6]+cc[7];
                unsigned s = tot;
#pragma unroll
                for (int off = 1; off <= 16; off <<= 1) {
                    unsigned v = __shfl_down_sync(0xFFFFFFFFu, s, off);
                    if (lane + off < 32) s += v;
                }
                unsigned run = s - tot;
#pragma unroll
                for (int j = 7; j >= 0; --j) {
                    unsigned nr = run + cc[j];
                    if (nr >= rcur && run < rcur) {
                        sb_b    = (unsigned)(lane * 8 + j);
                        sb_rank = rcur - run;
                        sb_m    = cc[j];
                    }
                    run = nr;
                }
            }
            __syncthreads();
            U  = (U << 8) | (sb_b ^ X);
            K  = (K << 8) | sb_b;
            rk = sb_rank;
            mm = sb_m;
            bits -= 8;
        }
        if (bits > 0) {
#pragma unroll
            for (int j = 0; j < 16; ++j) {
                bool valid = (j < 12) || has4;
                if (valid && (u[j] >> bits) == U) {
                    int p = atomicAdd(&gcount, 1);
                    if (p < 64) gbuf[p] = u2k(u[j]);
                }
            }
            __syncthreads();
            if (warp == 0) {
                int n = gcount; if (n > 64) n = 64;
                unsigned ck0 = (lane      < n) ? gbuf[lane]      : 0u;
                unsigned ck1 = (lane + 32 < n) ? gbuf[lane + 32] : 0u;
                bool a0 = (lane < n), a1 = (lane + 32 < n);
                unsigned r = rk;
                unsigned tk = K << bits;
                for (int b = bits - 1; b >= 0; --b) {
                    bool bit0 = ((ck0 >> b) & 1u) != 0u;
                    bool bit1 = ((ck1 >> b) & 1u) != 0u;
                    unsigned c = __popc(__ballot_sync(0xFFFFFFFFu, a0 && bit0))
                               + __popc(__ballot_sync(0xFFFFFFFFu, a1 && bit1));
                    if (c >= r) { a0 = a0 && bit0; a1 = a1 && bit1; tk |= (1u << b); }
                    else        { r -= c; a0 = a0 && !bit0; a1 = a1 && !bit1; }
                }
                if (lane == 0) sb_t = k2f(tk);
            }
        } else {
            if (tid == 0) sb_t = __uint_as_float(U);
        }
    }
    __syncthreads();                       // sb_t visible
    const float t = sb_t;

    // ---- mask + store: float compare ----
    float4* po = reinterpret_cast<float4*>(out + base);
#pragma unroll
    for (int s = 0; s < 4; ++s) {
        int p = tid + s * 256;
        if (s < 3 || has4) {
            float4 o;
            float fx = __uint_as_float(u[4*s+0]);
            float fy = __uint_as_float(u[4*s+1]);
            float fz = __uint_as_float(u[4*s+2]);
            float fw = __uint_as_float(u[4*s+3]);
            o.x = (fx < t) ? fx : 0.0f;
            o.y = (fy < t) ? fy : 0.0f;
            o.z = (fz < t) ? fz : 0.0f;
            o.w = (fw < t) ? fw : 0.0f;
            po[p] = o;
        }
    }
}

extern "C" void kernel_launch(void* const* d_in, const int* in_sizes, int n_in,
                              void* d_out, int out_size) {
    const float* x = (const float*)d_in[0];
    float* out = (float*)d_out;
    int rows = in_sizes[0] / NROW;   // 16384
    wta2d_kernel<<<rows, 256>>>(x, out);
}

// round 16
// speedup vs baseline: 1.1801x; 1.1801x over previous
#include <cuda_runtime.h>
#include <cuda_bf16.h>

// WTA2D: per (B,C) row of H*W=3136 fp32, t = 313th-largest, out = (t > x) ? x : 0.
//
// One CTA (256 thr) per row, row in registers (16 keys/thread).
// Round 1: 256-bucket shared ATOMIC histogram of top byte (all elems).
// Round 2: 256-bucket shared ATOMIC histogram of 2nd byte over winning bucket.
// -> 16-bit prefix resolved, bucket typically ~10-40 elems.
// Tail: gather <=64 candidates from registers, warp-0 ballot bisection over the
// remaining 16 bits (2 candidates/lane). Generic fallback (compact + 4-bit
// rounds) if the 16-bit bucket exceeds 64 elements.
//
// [Locked-in best variant after 15 rounds: all structural alternatives
//  (higher occupancy, persistence, prefetch pipelining, half-block phase
//  overlap, load de-batching, wider/windowed histograms) measured slower.]

#define NROW 3136
#define KSEL 313u

__device__ __forceinline__ unsigned f2k(float f) {
    unsigned u = __float_as_uint(f);
    return (u & 0x80000000u) ? ~u : (u | 0x80000000u);
}
__device__ __forceinline__ float k2f(unsigned k) {
    unsigned u = (k & 0x80000000u) ? (k ^ 0x80000000u) : ~k;
    return __uint_as_float(u);
}

__global__ void __launch_bounds__(256, 6)
wta2d_kernel(const float* __restrict__ x, float* __restrict__ out) {
    const int tid  = threadIdx.x;
    const int lane = tid & 31;
    const int warp = tid >> 5;
    const size_t base = (size_t)blockIdx.x * NROW;

    __shared__ unsigned histA[256];
    __shared__ unsigned histB[256];
    __shared__ unsigned buf[NROW];          // fallback only
    __shared__ uint4 wsum[8][4];            // fallback only
    __shared__ unsigned warpcnt[8];         // fallback only
    __shared__ unsigned sb_d, sb_rank, sb_m, sb_tkey;
    __shared__ unsigned gbuf[64];
    __shared__ int gcount;

    histA[tid] = 0u;
    histB[tid] = 0u;
    if (tid == 0) gcount = 0;

    // ---- load row -> keys in registers ----
    unsigned key[16];
    const bool has4 = (tid < 16);
    const float4* xin = reinterpret_cast<const float4*>(x + base);
#pragma unroll
    for (int s = 0; s < 4; ++s) {
        int p = tid + s * 256;
        if (s < 3 || has4) {
            float4 f = xin[p];
            key[4*s+0] = f2k(f.x); key[4*s+1] = f2k(f.y);
            key[4*s+2] = f2k(f.z); key[4*s+3] = f2k(f.w);
        } else {
            key[4*s+0] = key[4*s+1] = key[4*s+2] = key[4*s+3] = 0u;
        }
    }
    __syncthreads();                        // hist zeros visible

    // ---- round 1: top-byte histogram (shared atomics) ----
#pragma unroll
    for (int j = 0; j < 16; ++j) {
        bool valid = (j < 12) || has4;
        if (valid) atomicAdd(&histA[key[j] >> 24], 1u);
    }
    __syncthreads();

    if (warp == 0) {    // pick among 256: lane owns histA[lane*8 .. lane*8+7]
        const uint4* h4 = reinterpret_cast<const uint4*>(histA) + lane * 2;
        uint4 v0 = h4[0], v1 = h4[1];
        unsigned cc[8] = { v0.x, v0.y, v0.z, v0.w, v1.x, v1.y, v1.z, v1.w };
        unsigned tot = cc[0]+cc[1]+cc[2]+cc[3]+cc[4]+cc[5]+cc[6]+cc[7];
        unsigned s = tot;
#pragma unroll
        for (int off = 1; off <= 16; off <<= 1) {
            unsigned v = __shfl_down_sync(0xFFFFFFFFu, s, off);
            if (lane + off < 32) s += v;
        }
        unsigned run = s - tot;             // total in higher buckets
#pragma unroll
        for (int j = 7; j >= 0; --j) {
            unsigned nr = run + cc[j];
            if (nr >= KSEL && run < KSEL) {
                sb_d    = (unsigned)(lane * 8 + j);
                sb_rank = KSEL - run;
            }
            run = nr;
        }
    }
    __syncthreads();
    const unsigned d8 = sb_d;

    // ---- round 2: 2nd-byte histogram over bucket-d8 elems ----
#pragma unroll
    for (int j = 0; j < 16; ++j) {
        bool valid = (j < 12) || has4;
        if (valid && (key[j] >> 24) == d8)
            atomicAdd(&histB[(key[j] >> 16) & 0xFFu], 1u);
    }
    __syncthreads();

    if (warp == 0) {    // pick among 256 again
        unsigned rk1 = sb_rank;
        __syncwarp();
        const uint4* h4 = reinterpret_cast<const uint4*>(histB) + lane * 2;
        uint4 v0 = h4[0], v1 = h4[1];
        unsigned cc[8] = { v0.x, v0.y, v0.z, v0.w, v1.x, v1.y, v1.z, v1.w };
        unsigned tot = cc[0]+cc[1]+cc[2]+cc[3]+cc[4]+cc[5]+cc[6]+cc[7];
        unsigned s = tot;
#pragma unroll
        for (int off = 1; off <= 16; off <<= 1) {
            unsigned v = __shfl_down_sync(0xFFFFFFFFu, s, off);
            if (lane + off < 32) s += v;
        }
        unsigned run = s - tot;
#pragma unroll
        for (int j = 7; j >= 0; --j) {
            unsigned nr = run + cc[j];
            if (nr >= rk1 && run < rk1) {
                sb_d    = (d8 << 8) | (unsigned)(lane * 8 + j);
                sb_rank = rk1 - run;
                sb_m    = cc[j];
            }
            run = nr;
        }
    }
    __syncthreads();
    const unsigned prefix16 = sb_d;         // key >> 16 == prefix16
    const unsigned rk2 = sb_rank;
    const unsigned m2  = sb_m;

    if (m2 <= 64u) {
        // ---- fast tail: gather from registers, bisect low 16 bits ----
#pragma unroll
        for (int j = 0; j < 16; ++j) {
            bool valid = (j < 12) || has4;
            if (valid && (key[j] >> 16) == prefix16)
                gbuf[atomicAdd(&gcount, 1)] = key[j];
        }
        __syncthreads();
        if (warp == 0) {
            int n = gcount;
            unsigned ck0 = (lane      < n) ? gbuf[lane]      : 0u;
            unsigned ck1 = (lane + 32 < n) ? gbuf[lane + 32] : 0u;
            bool a0 = (lane < n), a1 = (lane + 32 < n);
            unsigned r = rk2;
            unsigned tk = prefix16 << 16;
#pragma unroll
            for (int b = 15; b >= 0; --b) {
                bool bit0 = ((ck0 >> b) & 1u) != 0u;
                bool bit1 = ((ck1 >> b) & 1u) != 0u;
                unsigned c = __popc(__ballot_sync(0xFFFFFFFFu, a0 && bit0))
                           + __popc(__ballot_sync(0xFFFFFFFFu, a1 && bit1));
                if (c >= r) { a0 = a0 && bit0; a1 = a1 && bit1; tk |= (1u << b); }
                else        { r -= c; a0 = a0 && !bit0; a1 = a1 && !bit1; }
            }
            if (lane == 0) sb_tkey = tk;
        }
        __syncthreads();
    } else {
        // ---- generic fallback: compact prefix16 bucket, 4-bit rounds ----
        unsigned mycnt = 0;
#pragma unroll
        for (int j = 0; j < 16; ++j) {
            bool valid = (j < 12) || has4;
            mycnt += (valid && (key[j] >> 16) == prefix16) ? 1u : 0u;
        }
        unsigned isum = mycnt;
#pragma unroll
        for (int off = 1; off <= 16; off <<= 1) {
            unsigned v = __shfl_up_sync(0xFFFFFFFFu, isum, off);
            if (lane >= off) isum += v;
        }
        if (lane == 31) warpcnt[warp] = isum;
        __syncthreads();
        unsigned pos = isum - mycnt;
#pragma unroll
        for (int w = 0; w < 8; ++w) pos += (w < warp) ? warpcnt[w] : 0u;
#pragma unroll
        for (int j = 0; j < 16; ++j) {
            bool valid = (j < 12) || has4;
            if (valid && (key[j] >> 16) == prefix16) buf[pos++] = key[j];
        }
        __syncthreads();

        unsigned prefix = prefix16, rk = rk2, mcur = m2;
        int shift = 12;
        while (mcur > 32 && shift >= 0) {
            unsigned long long acc = 0ull;
            int top = shift + 4;
            for (unsigned i = tid; i < m2; i += 256) {
                unsigned k = buf[i];
                if ((k >> top) == prefix) acc += 1ull << (((k >> shift) & 15u) * 4u);
            }
            {
                unsigned lo = (unsigned)acc, hi = (unsigned)(acc >> 32);
                unsigned r0 = (lo & 0x0F0F0F0Fu);
                unsigned r1 = ((lo >> 4) & 0x0F0F0F0Fu);
                unsigned r2 = (hi & 0x0F0F0F0Fu);
                unsigned r3 = ((hi >> 4) & 0x0F0F0F0Fu);
#pragma unroll
                for (int off = 1; off <= 4; off <<= 1) {
                    r0 += __shfl_xor_sync(0xFFFFFFFFu, r0, off);
                    r1 += __shfl_xor_sync(0xFFFFFFFFu, r1, off);
                    r2 += __shfl_xor_sync(0xFFFFFFFFu, r2, off);
                    r3 += __shfl_xor_sync(0xFFFFFFFFu, r3, off);
                }
                if ((lane & 7) == 0) wsum[warp][lane >> 3] = make_uint4(r0, r1, r2, r3);
            }
            __syncthreads();
            if (warp == 0) {
                unsigned cnt = 0;
                if (lane < 16) {
                    int word = (lane & 1) | ((lane >> 3) << 1);
                    int sh   = ((lane & 7) >> 1) * 8;
#pragma unroll
                    for (int w = 0; w < 8; ++w)
#pragma unroll
                        for (int g = 0; g < 4; ++g) {
                            const unsigned* ws = reinterpret_cast<const unsigned*>(&wsum[w][g]);
                            cnt += (ws[word] >> sh) & 0xFFu;
                        }
                }
                unsigned ssum = cnt;
#pragma unroll
                for (int off = 1; off <= 8; off <<= 1) {
                    unsigned v = __shfl_down_sync(0xFFFFFFFFu, ssum, off);
                    if (lane + off < 16) ssum += v;
                }
                if (lane < 16 && ssum >= rk && (ssum - cnt) < rk) {
                    sb_d    = (prefix << 4) | (unsigned)lane;
                    sb_rank = rk - (ssum - cnt);
                    sb_m    = cnt;
                }
            }
            __syncthreads();
            prefix = sb_d; rk = sb_rank; mcur = sb_m;
            shift -= 4;
        }

        int rem = shift + 4;
        if (rem > 0) {
            if (tid == 0) gcount = 0;
            __syncthreads();
            for (unsigned i = tid; i < m2; i += 256) {
                unsigned k = buf[i];
                if ((k >> rem) == prefix) {
                    int p = atomicAdd(&gcount, 1);
                    if (p < 32) gbuf[p] = k;
                }
            }
            __syncthreads();
            if (warp == 0) {
                int n = gcount; if (n > 32) n = 32;
                unsigned ck = (lane < n) ? gbuf[lane] : 0u;
                bool alive = (lane < n);
                unsigned r = rk;
                unsigned tk = prefix << rem;
                for (int b = rem - 1; b >= 0; --b) {
                    bool bit = ((ck >> b) & 1u) != 0u;
                    unsigned bal = __ballot_sync(0xFFFFFFFFu, alive && bit);
                    unsigned c = __popc(bal);
                    if (c >= r) { alive = alive && bit; tk |= (1u << b); }
                    else        { r -= c; alive = alive && !bit; }
                }
                if (lane == 0) sb_tkey = tk;
            }
        } else {
            if (tid == 0) sb_tkey = prefix;
        }
        __syncthreads();
    }
    const unsigned tkey = sb_tkey;

    // ---- mask + store (key < tkey  <=>  x < t) ----
    float4* po = reinterpret_cast<float4*>(out + base);
#pragma unroll
    for (int s2 = 0; s2 < 4; ++s2) {
        int p = tid + s2 * 256;
        if (s2 < 3 || has4) {
            float4 o;
            o.x = (key[4*s2+0] < tkey) ? k2f(key[4*s2+0]) : 0.0f;
            o.y = (key[4*s2+1] < tkey) ? k2f(key[4*s2+1]) : 0.0f;
            o.z = (key[4*s2+2] < tkey) ? k2f(key[4*s2+2]) : 0.0f;
            o.w = (key[4*s2+3] < tkey) ? k2f(key[4*s2+3]) : 0.0f;
            po[p] = o;
        }
    }
}

extern "C" void kernel_launch(void* const* d_in, const int* in_sizes, int n_in,
                              void* d_out, int out_size) {
    const float* x = (const float*)d_in[0];
    float* out = (float*)d_out;
    int rows = in_sizes[0] / NROW;   // 16384
    wta2d_kernel<<<rows, 256>>>(x, out);
}

// round 17
// speedup vs baseline: 1.1890x; 1.0075x over previous
#include <cuda_runtime.h>
#include <cuda_bf16.h>

// WTA2D: per (B,C) row of H*W=3136 fp32, t = 313th-largest, out = (t > x) ? x : 0.
//
// One CTA (256 thr) per row, row in registers (16 keys/thread).
// Round 1: 256-bucket shared ATOMIC histogram of top byte (all elems).
// Round 2: 256-bucket shared ATOMIC histogram of 2nd byte over winning bucket.
// -> 16-bit prefix resolved, bucket typically ~10-40 elems.
// Tail: gather <=64 candidates from registers, warp-0 ballot bisection over the
// remaining 16 bits (2 candidates/lane). Generic fallback (compact + 4-bit
// rounds) if the 16-bit bucket exceeds 64 elements.
//
// [FINAL: best measured variant (93.9-94.1us, reproduced twice). 15 structural
//  alternatives tested and falsified: higher occupancy, persistence, prefetch
//  pipelining, half-block phase overlap, load de-batching, windowed/wider
//  histograms, conflict-halving, raw-domain transforms — all equal or slower.]

#define NROW 3136
#define KSEL 313u

__device__ __forceinline__ unsigned f2k(float f) {
    unsigned u = __float_as_uint(f);
    return (u & 0x80000000u) ? ~u : (u | 0x80000000u);
}
__device__ __forceinline__ float k2f(unsigned k) {
    unsigned u = (k & 0x80000000u) ? (k ^ 0x80000000u) : ~k;
    return __uint_as_float(u);
}

__global__ void __launch_bounds__(256, 6)
wta2d_kernel(const float* __restrict__ x, float* __restrict__ out) {
    const int tid  = threadIdx.x;
    const int lane = tid & 31;
    const int warp = tid >> 5;
    const size_t base = (size_t)blockIdx.x * NROW;

    __shared__ unsigned histA[256];
    __shared__ unsigned histB[256];
    __shared__ unsigned buf[NROW];          // fallback only
    __shared__ uint4 wsum[8][4];            // fallback only
    __shared__ unsigned warpcnt[8];         // fallback only
    __shared__ unsigned sb_d, sb_rank, sb_m, sb_tkey;
    __shared__ unsigned gbuf[64];
    __shared__ int gcount;

    histA[tid] = 0u;
    histB[tid] = 0u;
    if (tid == 0) gcount = 0;

    // ---- load row -> keys in registers ----
    unsigned key[16];
    const bool has4 = (tid < 16);
    const float4* xin = reinterpret_cast<const float4*>(x + base);
#pragma unroll
    for (int s = 0; s < 4; ++s) {
        int p = tid + s * 256;
        if (s < 3 || has4) {
            float4 f = xin[p];
            key[4*s+0] = f2k(f.x); key[4*s+1] = f2k(f.y);
            key[4*s+2] = f2k(f.z); key[4*s+3] = f2k(f.w);
        } else {
            key[4*s+0] = key[4*s+1] = key[4*s+2] = key[4*s+3] = 0u;
        }
    }
    __syncthreads();                        // hist zeros visible

    // ---- round 1: top-byte histogram (shared atomics) ----
#pragma unroll
    for (int j = 0; j < 16; ++j) {
        bool valid = (j < 12) || has4;
        if (valid) atomicAdd(&histA[key[j] >> 24], 1u);
    }
    __syncthreads();

    if (warp == 0) {    // pick among 256: lane owns histA[lane*8 .. lane*8+7]
        const uint4* h4 = reinterpret_cast<const uint4*>(histA) + lane * 2;
        uint4 v0 = h4[0], v1 = h4[1];
        unsigned cc[8] = { v0.x, v0.y, v0.z, v0.w, v1.x, v1.y, v1.z, v1.w };
        unsigned tot = cc[0]+cc[1]+cc[2]+cc[3]+cc[4]+cc[5]+cc[6]+cc[7];
        unsigned s = tot;
#pragma unroll
        for (int off = 1; off <= 16; off <<= 1) {
            unsigned v = __shfl_down_sync(0xFFFFFFFFu, s, off);
            if (lane + off < 32) s += v;
        }
        unsigned run = s - tot;             // total in higher buckets
#pragma unroll
        for (int j = 7; j >= 0; --j) {
            unsigned nr = run + cc[j];
            if (nr >= KSEL && run < KSEL) {
                sb_d    = (unsigned)(lane * 8 + j);
                sb_rank = KSEL - run;
            }
            run = nr;
        }
    }
    __syncthreads();
    const unsigned d8 = sb_d;

    // ---- round 2: 2nd-byte histogram over bucket-d8 elems ----
#pragma unroll
    for (int j = 0; j < 16; ++j) {
        bool valid = (j < 12) || has4;
        if (valid && (key[j] >> 24) == d8)
            atomicAdd(&histB[(key[j] >> 16) & 0xFFu], 1u);
    }
    __syncthreads();

    if (warp == 0) {    // pick among 256 again
        unsigned rk1 = sb_rank;
        __syncwarp();
        const uint4* h4 = reinterpret_cast<const uint4*>(histB) + lane * 2;
        uint4 v0 = h4[0], v1 = h4[1];
        unsigned cc[8] = { v0.x, v0.y, v0.z, v0.w, v1.x, v1.y, v1.z, v1.w };
        unsigned tot = cc[0]+cc[1]+cc[2]+cc[3]+cc[4]+cc[5]+cc[6]+cc[7];
        unsigned s = tot;
#pragma unroll
        for (int off = 1; off <= 16; off <<= 1) {
            unsigned v = __shfl_down_sync(0xFFFFFFFFu, s, off);
            if (lane + off < 32) s += v;
        }
        unsigned run = s - tot;
#pragma unroll
        for (int j = 7; j >= 0; --j) {
            unsigned nr = run + cc[j];
            if (nr >= rk1 && run < rk1) {
                sb_d    = (d8 << 8) | (unsigned)(lane * 8 + j);
                sb_rank = rk1 - run;
                sb_m    = cc[j];
            }
            run = nr;
        }
    }
    __syncthreads();
    const unsigned prefix16 = sb_d;         // key >> 16 == prefix16
    const unsigned rk2 = sb_rank;
    const unsigned m2  = sb_m;

    if (m2 <= 64u) {
        // ---- fast tail: gather from registers, bisect low 16 bits ----
#pragma unroll
        for (int j = 0; j < 16; ++j) {
            bool valid = (j < 12) || has4;
            if (valid && (key[j] >> 16) == prefix16)
                gbuf[atomicAdd(&gcount, 1)] = key[j];
        }
        __syncthreads();
        if (warp == 0) {
            int n = gcount;
            unsigned ck0 = (lane      < n) ? gbuf[lane]      : 0u;
            unsigned ck1 = (lane + 32 < n) ? gbuf[lane + 32] : 0u;
            bool a0 = (lane < n), a1 = (lane + 32 < n);
            unsigned r = rk2;
            unsigned tk = prefix16 << 16;
#pragma unroll
            for (int b = 15; b >= 0; --b) {
                bool bit0 = ((ck0 >> b) & 1u) != 0u;
                bool bit1 = ((ck1 >> b) & 1u) != 0u;
                unsigned c = __popc(__ballot_sync(0xFFFFFFFFu, a0 && bit0))
                           + __popc(__ballot_sync(0xFFFFFFFFu, a1 && bit1));
                if (c >= r) { a0 = a0 && bit0; a1 = a1 && bit1; tk |= (1u << b); }
                else        { r -= c; a0 = a0 && !bit0; a1 = a1 && !bit1; }
            }
            if (lane == 0) sb_tkey = tk;
        }
        __syncthreads();
    } else {
        // ---- generic fallback: compact prefix16 bucket, 4-bit rounds ----
        unsigned mycnt = 0;
#pragma unroll
        for (int j = 0; j < 16; ++j) {
            bool valid = (j < 12) || has4;
            mycnt += (valid && (key[j] >> 16) == prefix16) ? 1u : 0u;
        }
        unsigned isum = mycnt;
#pragma unroll
        for (int off = 1; off <= 16; off <<= 1) {
            unsigned v = __shfl_up_sync(0xFFFFFFFFu, isum, off);
            if (lane >= off) isum += v;
        }
        if (lane == 31) warpcnt[warp] = isum;
        __syncthreads();
        unsigned pos = isum - mycnt;
#pragma unroll
        for (int w = 0; w < 8; ++w) pos += (w < warp) ? warpcnt[w] : 0u;
#pragma unroll
        for (int j = 0; j < 16; ++j) {
            bool valid = (j < 12) || has4;
            if (valid && (key[j] >> 16) == prefix16) buf[pos++] = key[j];
        }
        __syncthreads();

        unsigned prefix = prefix16, rk = rk2, mcur = m2;
        int shift = 12;
        while (mcur > 32 && shift >= 0) {
            unsigned long long acc = 0ull;
            int top = shift + 4;
            for (unsigned i = tid; i < m2; i += 256) {
                unsigned k = buf[i];
                if ((k >> top) == prefix) acc += 1ull << (((k >> shift) & 15u) * 4u);
            }
            {
                unsigned lo = (unsigned)acc, hi = (unsigned)(acc >> 32);
                unsigned r0 = (lo & 0x0F0F0F0Fu);
                unsigned r1 = ((lo >> 4) & 0x0F0F0F0Fu);
                unsigned r2 = (hi & 0x0F0F0F0Fu);
                unsigned r3 = ((hi >> 4) & 0x0F0F0F0Fu);
#pragma unroll
                for (int off = 1; off <= 4; off <<= 1) {
                    r0 += __shfl_xor_sync(0xFFFFFFFFu, r0, off);
                    r1 += __shfl_xor_sync(0xFFFFFFFFu, r1, off);
                    r2 += __shfl_xor_sync(0xFFFFFFFFu, r2, off);
                    r3 += __shfl_xor_sync(0xFFFFFFFFu, r3, off);
                }
                if ((lane & 7) == 0) wsum[warp][lane >> 3] = make_uint4(r0, r1, r2, r3);
            }
            __syncthreads();
            if (warp == 0) {
                unsigned cnt = 0;
                if (lane < 16) {
                    int word = (lane & 1) | ((lane >> 3) << 1);
                    int sh   = ((lane & 7) >> 1) * 8;
#pragma unroll
                    for (int w = 0; w < 8; ++w)
#pragma unroll
                        for (int g = 0; g < 4; ++g) {
                            const unsigned* ws = reinterpret_cast<const unsigned*>(&wsum[w][g]);
                            cnt += (ws[word] >> sh) & 0xFFu;
                        }
                }
                unsigned ssum = cnt;
#pragma unroll
                for (int off = 1; off <= 8; off <<= 1) {
                    unsigned v = __shfl_down_sync(0xFFFFFFFFu, ssum, off);
                    if (lane + off < 16) ssum += v;
                }
                if (lane < 16 && ssum >= rk && (ssum - cnt) < rk) {
                    sb_d    = (prefix << 4) | (unsigned)lane;
                    sb_rank = rk - (ssum - cnt);
                    sb_m    = cnt;
                }
            }
            __syncthreads();
            prefix = sb_d; rk = sb_rank; mcur = sb_m;
            shift -= 4;
        }

        int rem = shift + 4;
        if (rem > 0) {
            if (tid == 0) gcount = 0;
            __syncthreads();
            for (unsigned i = tid; i < m2; i += 256) {
                unsigned k = buf[i];
                if ((k >> rem) == prefix) {
                    int p = atomicAdd(&gcount, 1);
                    if (p < 32) gbuf[p] = k;
                }
            }
            __syncthreads();
            if (warp == 0) {
                int n = gcount; if (n > 32) n = 32;
                unsigned ck = (lane < n) ? gbuf[lane] : 0u;
                bool alive = (lane < n);
                unsigned r = rk;
                unsigned tk = prefix << rem;
                for (int b = rem - 1; b >= 0; --b) {
                    bool bit = ((ck >> b) & 1u) != 0u;
                    unsigned bal = __ballot_sync(0xFFFFFFFFu, alive && bit);
                    unsigned c = __popc(bal);
                    if (c >= r) { alive = alive && bit; tk |= (1u << b); }
                    else        { r -= c; alive = alive && !bit; }
                }
                if (lane == 0) sb_tkey = tk;
            }
        } else {
            if (tid == 0) sb_tkey = prefix;
        }
        __syncthreads();
    }
    const unsigned tkey = sb_tkey;

    // ---- mask + store (key < tkey  <=>  x < t) ----
    float4* po = reinterpret_cast<float4*>(out + base);
#pragma unroll
    for (int s2 = 0; s2 < 4; ++s2) {
        int p = tid + s2 * 256;
        if (s2 < 3 || has4) {
            float4 o;
            o.x = (key[4*s2+0] < tkey) ? k2f(key[4*s2+0]) : 0.0f;
            o.y = (key[4*s2+1] < tkey) ? k2f(key[4*s2+1]) : 0.0f;
            o.z = (key[4*s2+2] < tkey) ? k2f(key[4*s2+2]) : 0.0f;
            o.w = (key[4*s2+3] < tkey) ? k2f(key[4*s2+3]) : 0.0f;
            po[p] = o;
        }
    }
}

extern "C" void kernel_launch(void* const* d_in, const int* in_sizes, int n_in,
                              void* d_out, int out_size) {
    const float* x = (const float*)d_in[0];
    float* out = (float*)d_out;
    int rows = in_sizes[0] / NROW;   // 16384
    wta2d_kernel<<<rows, 256>>>(x, out);
}